// round 15
// baseline (speedup 1.0000x reference)
#include <cuda_runtime.h>
#include <cuda_fp16.h>
#include <cstdint>

#define M_TOT 32768
#define K_TOT 8192
#define D_DIM 512
#define BM 128
#define BN 256

#define A_TILE_HALF 4096              // per (mtile,kt): hi plane (2048 halves used)
#define B_TILE_HALF 8192              // per (g,kt): interleaved hi|lo frag layout (phase2)
#define B1_TILE_HALF 4096             // per (g,kt): hi-only pair-packed (phase1)

#define EPS_ACC 0.015f
#define MAX_CAND 8

// ---- device scratch -----------------------------------------------------------
__device__ float    g_hn[K_TOT];
__device__ int      g_idx[M_TOT];
__device__ __half   g_A [(size_t)M_TOT * D_DIM * 2];
__device__ __half   g_A2[(size_t)M_TOT * D_DIM * 2];
__device__ __half   g_B [(size_t)K_TOT * D_DIM * 2];
__device__ __half   g_Bh1[(size_t)K_TOT * D_DIM];
__device__ float    g_T[M_TOT];
__device__ int      g_dirty[M_TOT];                    // full-GEMM fallback tokens
__device__ int      g_cnt;
__device__ unsigned long long g_key[M_TOT];            // 0 = clean; else packed (score,~idx)
__device__ unsigned g_mbh_bits, g_mbl_bits;
// phase1 per-lane records, transposed for coalesced merge reads: [unit(64)][tok]
__device__ float    g_l1[64 * M_TOT];
__device__ float    g_l2[64 * M_TOT];
__device__ int      g_li[64 * M_TOT];
// rescore lists
__device__ int      g_rtok[M_TOT * MAX_CAND];
__device__ int      g_rcode[M_TOT * MAX_CAND];
__device__ int      g_rcnt;

// ---- helpers --------------------------------------------------------------------
__device__ __forceinline__ uint32_t smem_u32(const void* p) {
    uint32_t a;
    asm("{ .reg .u64 t; cvta.to.shared.u64 t, %1; cvt.u32.u64 %0, t; }" : "=r"(a) : "l"(p));
    return a;
}
__device__ __forceinline__ void cp16(uint32_t dst, const void* src) {
    asm volatile("cp.async.cg.shared.global [%0], [%1], 16;" :: "r"(dst), "l"(src) : "memory");
}
#define CP_COMMIT() asm volatile("cp.async.commit_group;" ::: "memory")
#define CP_WAIT3()  asm volatile("cp.async.wait_group 3;" ::: "memory")
#define CP_WAIT2()  asm volatile("cp.async.wait_group 2;" ::: "memory")
#define CP_WAIT1()  asm volatile("cp.async.wait_group 1;" ::: "memory")
#define CP_WAIT0()  asm volatile("cp.async.wait_group 0;" ::: "memory")

__device__ __forceinline__ void mma16(float* c, const uint4& a, uint32_t b0, uint32_t b1) {
    asm volatile(
        "mma.sync.aligned.m16n8k16.row.col.f32.f16.f16.f32 "
        "{%0,%1,%2,%3}, {%4,%5,%6,%7}, {%8,%9}, {%0,%1,%2,%3};"
        : "+f"(c[0]), "+f"(c[1]), "+f"(c[2]), "+f"(c[3])
        : "r"(a.x), "r"(a.y), "r"(a.z), "r"(a.w), "r"(b0), "r"(b1));
}

// ---- prep ------------------------------------------------------------------------
__global__ void pack_ze(const float* __restrict__ ze) {
    int idx  = blockIdx.x * blockDim.x + threadIdx.x;
    int lane = idx & 31, mblk = (idx >> 5) & 7, kt = (idx >> 8) & 31, mt = idx >> 13;
    int q = lane >> 2, r4 = lane & 3;
    __half hi[8];
#pragma unroll
    for (int jj = 0; jj < 4; ++jj) {
        int rhalf = jj & 1, khalf = jj >> 1;
        int m = mt * 128 + mblk * 16 + rhalf * 8 + q;
        int d = kt * 16 + khalf * 8 + r4 * 2;
        float2 f = *reinterpret_cast<const float2*>(ze + (size_t)m * D_DIM + d);
        hi[jj * 2 + 0] = __float2half_rn(f.x);
        hi[jj * 2 + 1] = __float2half_rn(f.y);
    }
    size_t base = ((size_t)(mt * 32 + kt)) * A_TILE_HALF + (size_t)(mblk * 32 + lane) * 8;
    *reinterpret_cast<uint4*>(&g_A[base]) = *reinterpret_cast<uint4*>(hi);
}
__global__ void pack_cb(const float* __restrict__ cb) {
    int i = blockIdx.x * blockDim.x + threadIdx.x;
    float f = cb[i];
    __half hi = __float2half_rn(f);
    __half lo = __float2half_rn(f - __half2float(hi));
    int n = i >> 9, d = i & 511;
    int g = n >> 8, nr = n & 255, nblk = nr >> 3, q = nr & 7;
    int kt = d >> 4, kk = d & 15, par = kk & 1, r4 = (kk >> 1) & 3, khalf = kk >> 3;
    int lane = q * 4 + r4;
    size_t base = ((size_t)(g * 32 + kt)) * B_TILE_HALF + (size_t)(nblk * 32 + lane) * 8;
    g_B[base + khalf * 2 + par]     = hi;
    g_B[base + 4 + khalf * 2 + par] = lo;
    int pair = nblk >> 1, side = nblk & 1;
    size_t b1 = ((size_t)(g * 32 + kt)) * B1_TILE_HALF + (size_t)(pair * 32 + lane) * 8;
    g_Bh1[b1 + side * 4 + khalf * 2 + par] = hi;
}
__global__ void norm_cb(const float* __restrict__ cb) {
    int code = (blockIdx.x * blockDim.x + threadIdx.x) >> 5;
    int lane = threadIdx.x & 31;
    const float4* row = reinterpret_cast<const float4*>(cb + (size_t)code * D_DIM);
    float s = 0.0f, nh2 = 0.0f, nl2 = 0.0f;
#pragma unroll
    for (int t = 0; t < 4; ++t) {
        float4 v = row[lane + 32 * t];
        float vv[4] = { v.x, v.y, v.z, v.w };
#pragma unroll
        for (int e = 0; e < 4; ++e) {
            float f = vv[e];
            s += f * f;
            float h = __half2float(__float2half_rn(f));
            float l = __half2float(__float2half_rn(f - h));
            nh2 += h * h;
            nl2 += l * l;
        }
    }
#pragma unroll
    for (int off = 16; off > 0; off >>= 1) {
        s   += __shfl_xor_sync(0xffffffffu, s, off);
        nh2 += __shfl_xor_sync(0xffffffffu, nh2, off);
        nl2 += __shfl_xor_sync(0xffffffffu, nl2, off);
    }
    if (lane == 0) {
        g_hn[code] = 0.5f * s;
        atomicMax(&g_mbh_bits, __float_as_uint(sqrtf(nh2)));
        atomicMax(&g_mbl_bits, __float_as_uint(sqrtf(nl2)));
    }
}
__global__ void norm_z(const float* __restrict__ ze) {
    if (blockIdx.x == 0 && threadIdx.x == 0) { g_cnt = 0; g_rcnt = 0; }
    int tok  = (blockIdx.x * blockDim.x + threadIdx.x) >> 5;
    int lane = threadIdx.x & 31;
    const float4* row = reinterpret_cast<const float4*>(ze + (size_t)tok * D_DIM);
    float nh2 = 0.0f, nl2 = 0.0f;
#pragma unroll
    for (int t = 0; t < 4; ++t) {
        float4 v = row[lane + 32 * t];
        float vv[4] = { v.x, v.y, v.z, v.w };
#pragma unroll
        for (int e = 0; e < 4; ++e) {
            float f = vv[e];
            float h = __half2float(__float2half_rn(f));
            float l = __half2float(__float2half_rn(f - h));
            nh2 += h * h;
            nl2 += l * l;
        }
    }
#pragma unroll
    for (int off = 16; off > 0; off >>= 1) {
        nh2 += __shfl_xor_sync(0xffffffffu, nh2, off);
        nl2 += __shfl_xor_sync(0xffffffffu, nl2, off);
    }
    if (lane == 0) {
        float mbh = __uint_as_float(g_mbh_bits);
        float mbl = __uint_as_float(g_mbl_bits);
        float anh = sqrtf(nh2), anl = sqrtf(nl2);
        g_T[tok] = anh * mbl + anl * mbh + anl * mbl + EPS_ACC;
        g_key[tok] = 0ull;
    }
}

// ---- PHASE 1: hh-only GEMM + per-lane top-2, K split x4, 4-deep pipeline -------------
#define P1_PAIR 24576
#define P1_STAGES 6
#define P1_SMEM (P1_STAGES * P1_PAIR)
#define P1_PAIRS 128
__global__ void __launch_bounds__(512, 1) phase1_kernel() {
    extern __shared__ __align__(16) char smem[];
    const uint32_t sbase = smem_u32(smem);
    const int tid = threadIdx.x, wid = tid >> 5, lane = tid & 31;
    const int wm = wid >> 2, wn = wid & 3, q = lane >> 2, r4 = lane & 3;
    const int mtile = blockIdx.x >> 2, ks = blockIdx.x & 3;
    const int m0 = mtile * BM;

    float acc[2][8][4];
    float t1[2][2], t2[2][2];
    int   ti[2][2];
#pragma unroll
    for (int mf = 0; mf < 2; ++mf)
#pragma unroll
        for (int h = 0; h < 2; ++h) { t1[mf][h] = -3.0e38f; t2[mf][h] = -3.0e38f; ti[mf][h] = 0; }
#pragma unroll
    for (int mf = 0; mf < 2; ++mf)
#pragma unroll
        for (int nf = 0; nf < 8; ++nf)
#pragma unroll
            for (int c = 0; c < 4; ++c) acc[mf][nf][c] = 0.0f;

    auto issue_pair = [&](int p) {
        const int t0 = 2 * p, kt = t0 & 31, g = ks * 8 + (t0 >> 5);
        const uint32_t stw = sbase + (uint32_t)(p % P1_STAGES) * P1_PAIR;
        const __half* aG = g_A   + ((size_t)(mtile * 32) + kt) * A_TILE_HALF;
        const __half* bG = g_Bh1 + ((size_t)(g * 32 + kt)) * B1_TILE_HALF;
        int sub = tid >> 8, off = tid & 255;
        cp16(stw + sub * 4096 + off * 16, aG + (size_t)sub * A_TILE_HALF + off * 8);
#pragma unroll
        for (int i = 0; i < 2; ++i) {
            int seg = tid + i * 512;
            cp16(stw + 8192 + seg * 16, bG + (size_t)seg * 8);
        }
        CP_COMMIT();
    };
    issue_pair(0); issue_pair(1); issue_pair(2); issue_pair(3);

    for (int p = 0; p < P1_PAIRS; ++p) {
        if (p < P1_PAIRS - 3)       { CP_WAIT3(); }
        else if (p == P1_PAIRS - 3) { CP_WAIT2(); }
        else if (p == P1_PAIRS - 2) { CP_WAIT1(); }
        else                        { CP_WAIT0(); }
        __syncthreads();
        if (p + 4 < P1_PAIRS) issue_pair(p + 4);

        const char* stg = smem + (p % P1_STAGES) * P1_PAIR;
#pragma unroll
        for (int sub = 0; sub < 2; ++sub) {
            const char* stA = stg + sub * 4096;
            const char* stB = stg + 8192 + sub * 8192;
            uint4 ah0 = *reinterpret_cast<const uint4*>(stA + (size_t)((wm * 2 + 0) * 32 + lane) * 16);
            uint4 ah1 = *reinterpret_cast<const uint4*>(stA + (size_t)((wm * 2 + 1) * 32 + lane) * 16);
#pragma unroll
            for (int p4 = 0; p4 < 4; ++p4) {
                uint4 b = *reinterpret_cast<const uint4*>(
                    stB + (size_t)((wn * 4 + p4) * 32 + lane) * 16);
                mma16(acc[0][2 * p4],     ah0, b.x, b.y);
                mma16(acc[1][2 * p4],     ah1, b.x, b.y);
                mma16(acc[0][2 * p4 + 1], ah0, b.z, b.w);
                mma16(acc[1][2 * p4 + 1], ah1, b.z, b.w);
            }
        }

        if ((p & 15) == 15) {
            const int g = ks * 8 + (p >> 4);
#pragma unroll
            for (int nf = 0; nf < 8; ++nf) {
                int gc = g * BN + wn * 64 + nf * 8 + 2 * r4;
                float h0 = __ldg(&g_hn[gc]), h1 = __ldg(&g_hn[gc + 1]);
#pragma unroll
                for (int mf = 0; mf < 2; ++mf) {
                    float s0 = acc[mf][nf][0] - h0, s1 = acc[mf][nf][1] - h1;
                    float s2 = acc[mf][nf][2] - h0, s3 = acc[mf][nf][3] - h1;
                    if (s0 > t1[mf][0]) { t2[mf][0] = t1[mf][0]; t1[mf][0] = s0; ti[mf][0] = gc; }
                    else if (s0 > t2[mf][0]) t2[mf][0] = s0;
                    if (s1 > t1[mf][0]) { t2[mf][0] = t1[mf][0]; t1[mf][0] = s1; ti[mf][0] = gc + 1; }
                    else if (s1 > t2[mf][0]) t2[mf][0] = s1;
                    if (s2 > t1[mf][1]) { t2[mf][1] = t1[mf][1]; t1[mf][1] = s2; ti[mf][1] = gc; }
                    else if (s2 > t2[mf][1]) t2[mf][1] = s2;
                    if (s3 > t1[mf][1]) { t2[mf][1] = t1[mf][1]; t1[mf][1] = s3; ti[mf][1] = gc + 1; }
                    else if (s3 > t2[mf][1]) t2[mf][1] = s3;
                    acc[mf][nf][0] = 0.0f; acc[mf][nf][1] = 0.0f;
                    acc[mf][nf][2] = 0.0f; acc[mf][nf][3] = 0.0f;
                }
            }
        }
    }

    // Per-lane records, transposed layout [unit][tok]; unit = ks*16 + wn*4 + r4.
    const int unit = ks * 16 + wn * 4 + r4;
#pragma unroll
    for (int mf = 0; mf < 2; ++mf)
#pragma unroll
        for (int h = 0; h < 2; ++h) {
            int row = wm * 32 + mf * 16 + h * 8 + q;
            size_t slot = (size_t)unit * M_TOT + (m0 + row);
            g_l1[slot] = t1[mf][h];
            g_l2[slot] = t2[mf][h];
            g_li[slot] = ti[mf][h];
        }
}

// ---- merge: lane-level certification ---------------------------------------------------
__global__ void p1_merge() {
    int tok = blockIdx.x * blockDim.x + threadIdx.x;
    float H1 = -3.0e38f, mT2 = -3.0e38f;
    int bi = 0;
    for (int u = 0; u < 64; ++u) {
        size_t s = (size_t)u * M_TOT + tok;
        float o1 = g_l1[s];
        int   oi = g_li[s];
        if (o1 > H1 || (o1 == H1 && oi < bi)) { mT2 = fmaxf(mT2, H1); H1 = o1; bi = oi; }
        else mT2 = fmaxf(mT2, o1);
        mT2 = fmaxf(mT2, g_l2[s]);
    }
    float thr = H1 - 2.0f * g_T[tok];
    g_idx[tok] = bi;
    if (mT2 < thr) return;                             // certified clean

    int cand[MAX_CAND];
    int nc = 0;
    bool overflow = false;
    for (int u = 0; u < 64 && !overflow; ++u) {
        size_t s = (size_t)u * M_TOT + tok;
        if (g_l2[s] >= thr) overflow = true;
        float o1 = g_l1[s];
        if (o1 >= thr) {
            if (nc < MAX_CAND) cand[nc++] = g_li[s];
            else overflow = true;
        }
    }
    if (overflow) {
        int pos = atomicAdd(&g_cnt, 1);
        g_dirty[pos] = tok;
        return;
    }
    int rb = atomicAdd(&g_rcnt, nc);
    for (int c = 0; c < nc; ++c) { g_rtok[rb + c] = tok; g_rcode[rb + c] = cand[c]; }
}

// ---- exact fp32 rescore: one warp per (token, candidate) -------------------------------
__global__ void rescore_kernel(const float* __restrict__ ze, const float* __restrict__ cb) {
    int w    = (blockIdx.x * blockDim.x + threadIdx.x) >> 5;
    int lane = threadIdx.x & 31;
    int nw   = (gridDim.x * blockDim.x) >> 5;
    int total = g_rcnt;
    for (int p = w; p < total; p += nw) {
        int tok = g_rtok[p], code = g_rcode[p];
        const float4* za = reinterpret_cast<const float4*>(ze + (size_t)tok  * D_DIM);
        const float4* ca = reinterpret_cast<const float4*>(cb + (size_t)code * D_DIM);
        float s = 0.0f;
#pragma unroll
        for (int t = 0; t < 4; ++t) {
            float4 a = za[lane + 32 * t], b = ca[lane + 32 * t];
            s += a.x * b.x + a.y * b.y + a.z * b.z + a.w * b.w;
        }
#pragma unroll
        for (int off = 16; off > 0; off >>= 1) s += __shfl_xor_sync(0xffffffffu, s, off);
        if (lane == 0) {
            float sc = s - g_hn[code];
            uint32_t ub = __float_as_uint(sc);
            ub = (sc >= 0.0f) ? (ub | 0x80000000u) : ~ub;
            unsigned long long key = ((unsigned long long)ub << 32) | (unsigned)(~code);
            atomicMax(&g_key[tok], key);
        }
    }
}

// ---- full-GEMM fallback (rare): repack + 3-term, K split x32 ---------------------------
__global__ void phase2a(const float* __restrict__ ze) {
    int total = g_cnt * 512;
    for (int i = blockIdx.x * blockDim.x + threadIdx.x; i < total;
         i += gridDim.x * blockDim.x) {
        int s = i >> 9, d = i & 511;
        int tok = g_dirty[s];
        float f = ze[(size_t)tok * D_DIM + d];
        __half hi = __float2half_rn(f);
        __half lo = __float2half_rn(f - __half2float(hi));
        int mt = s >> 7, mr = s & 127, mblk = mr >> 4, row = mr & 15;
        int q = row & 7, rhalf = row >> 3;
        int kt = d >> 4, kk = d & 15, par = kk & 1, r4 = (kk >> 1) & 3, khalf = kk >> 3;
        int lane = q * 4 + r4, reg = rhalf + 2 * khalf;
        size_t base = ((size_t)(mt * 32 + kt)) * A_TILE_HALF + (size_t)(mblk * 32 + lane) * 8;
        g_A2[base + reg * 2 + par]        = hi;
        g_A2[base + 2048 + reg * 2 + par] = lo;
    }
}
#define P2_STG 24576
#define P2_SCR (3 * P2_STG)
#define P2_SMEM (P2_SCR + 4096)
#define P2_TILES 32
__global__ void __launch_bounds__(512, 1) phase2b_kernel() {
    const int cnt = g_cnt;
    const int mtile = blockIdx.x >> 5;
    const int ks    = blockIdx.x & 31;
    if (mtile * BM >= cnt) return;

    extern __shared__ __align__(16) char smem[];
    const uint32_t sbase = smem_u32(smem);
    const int tid = threadIdx.x, wid = tid >> 5, lane = tid & 31;
    const int wm = wid >> 2, wn = wid & 3, q = lane >> 2, r4 = lane & 3;
    const int m0 = mtile * BM;

    float* s_sb = reinterpret_cast<float*>(smem + P2_SCR);
    int*   s_si = reinterpret_cast<int*>(smem + P2_SCR + 2048);

    float acc[2][8][4];
#pragma unroll
    for (int mf = 0; mf < 2; ++mf)
#pragma unroll
        for (int nf = 0; nf < 8; ++nf)
#pragma unroll
            for (int c = 0; c < 4; ++c) acc[mf][nf][c] = 0.0f;

    auto issue_tile = [&](int t) {
        const uint32_t stw = sbase + (uint32_t)(t % 3) * P2_STG;
        const __half* aG = g_A2 + ((size_t)(mtile * 32) + t) * A_TILE_HALF;
        const __half* bG = g_B  + ((size_t)(ks * 32 + t)) * B_TILE_HALF;
        cp16(stw + tid * 16, aG + tid * 8);
#pragma unroll
        for (int i = 0; i < 2; ++i) {
            int seg = tid + i * 512;
            cp16(stw + 8192 + seg * 16, bG + seg * 8);
        }
        CP_COMMIT();
    };
    issue_tile(0); issue_tile(1);

    for (int t = 0; t < P2_TILES; ++t) {
        if (t < P2_TILES - 1) { CP_WAIT1(); } else { CP_WAIT0(); }
        __syncthreads();
        if (t + 2 < P2_TILES) issue_tile(t + 2);

        const char* st = smem + (t % 3) * P2_STG;
        uint4 ah[2], al[2];
#pragma unroll
        for (int mf = 0; mf < 2; ++mf) {
            ah[mf] = *reinterpret_cast<const uint4*>(
                st + (size_t)((wm * 2 + mf) * 32 + lane) * 16);
            al[mf] = *reinterpret_cast<const uint4*>(
                st + 4096 + (size_t)((wm * 2 + mf) * 32 + lane) * 16);
        }
#pragma unroll
        for (int nf = 0; nf < 8; ++nf) {
            uint4 b = *reinterpret_cast<const uint4*>(
                st + 8192 + (size_t)((wn * 8 + nf) * 32 + lane) * 16);
#pragma unroll
            for (int mf = 0; mf < 2; ++mf) {
                mma16(acc[mf][nf], ah[mf], b.x, b.y);
                mma16(acc[mf][nf], ah[mf], b.z, b.w);
                mma16(acc[mf][nf], al[mf], b.x, b.y);
            }
        }
    }

    float bestv[2][2];
    int   besti[2][2];
#pragma unroll
    for (int mf = 0; mf < 2; ++mf)
#pragma unroll
        for (int h = 0; h < 2; ++h) { bestv[mf][h] = -3.0e38f; besti[mf][h] = 0; }
#pragma unroll
    for (int nf = 0; nf < 8; ++nf) {
        int gc = ks * BN + wn * 64 + nf * 8 + 2 * r4;
        float h0 = __ldg(&g_hn[gc]), h1 = __ldg(&g_hn[gc + 1]);
#pragma unroll
        for (int mf = 0; mf < 2; ++mf) {
            float s0 = acc[mf][nf][0] - h0, s1 = acc[mf][nf][1] - h1;
            float s2 = acc[mf][nf][2] - h0, s3 = acc[mf][nf][3] - h1;
            if (s0 > bestv[mf][0]) { bestv[mf][0] = s0; besti[mf][0] = gc; }
            if (s1 > bestv[mf][0]) { bestv[mf][0] = s1; besti[mf][0] = gc + 1; }
            if (s2 > bestv[mf][1]) { bestv[mf][1] = s2; besti[mf][1] = gc; }
            if (s3 > bestv[mf][1]) { bestv[mf][1] = s3; besti[mf][1] = gc + 1; }
        }
    }
#pragma unroll
    for (int off = 1; off <= 2; off <<= 1) {
#pragma unroll
        for (int mf = 0; mf < 2; ++mf)
#pragma unroll
            for (int h = 0; h < 2; ++h) {
                float ov = __shfl_xor_sync(0xffffffffu, bestv[mf][h], off);
                int   oi = __shfl_xor_sync(0xffffffffu, besti[mf][h], off);
                if (ov > bestv[mf][h] || (ov == bestv[mf][h] && oi < besti[mf][h])) {
                    bestv[mf][h] = ov; besti[mf][h] = oi;
                }
            }
    }
    if (r4 == 0) {
#pragma unroll
        for (int mf = 0; mf < 2; ++mf)
#pragma unroll
            for (int h = 0; h < 2; ++h) {
                int rl = wm * 32 + mf * 16 + h * 8 + q;
                s_sb[rl * 4 + wn] = bestv[mf][h];
                s_si[rl * 4 + wn] = besti[mf][h];
            }
    }
    __syncthreads();
    if (tid < BM && (m0 + tid) < cnt) {
        float bv = s_sb[tid * 4]; int bi = s_si[tid * 4];
#pragma unroll
        for (int w = 1; w < 4; ++w) {
            float ov = s_sb[tid * 4 + w]; int oi = s_si[tid * 4 + w];
            if (ov > bv || (ov == bv && oi < bi)) { bv = ov; bi = oi; }
        }
        uint32_t ub = __float_as_uint(bv);
        ub = (bv >= 0.0f) ? (ub | 0x80000000u) : ~ub;
        unsigned long long key = ((unsigned long long)ub << 32) | (unsigned)(~bi);
        atomicMax(&g_key[g_dirty[m0 + tid]], key);
    }
}

// ---- gather (fused finalize: decode g_key when the token was repaired) -----------------
__global__ void gather_kernel(const float* __restrict__ cb, float* __restrict__ out) {
    int m = blockIdx.x;
    unsigned long long key = g_key[m];
    int k = key ? (int)(~(unsigned)(key & 0xFFFFFFFFull)) : g_idx[m];
    const float4* src = reinterpret_cast<const float4*>(cb + (size_t)k * D_DIM);
    float4*       dst = reinterpret_cast<float4*>(out + (size_t)m * D_DIM);
    dst[threadIdx.x] = src[threadIdx.x];
}

// ---- entry ------------------------------------------------------------------------------
extern "C" void kernel_launch(void* const* d_in, const int* in_sizes, int n_in,
                              void* d_out, int out_size) {
    const float* ze = (const float*)d_in[0];
    const float* cb = (const float*)d_in[1];
    float* out = (float*)d_out;

    cudaFuncSetAttribute(phase1_kernel,  cudaFuncAttributeMaxDynamicSharedMemorySize, P1_SMEM);
    cudaFuncSetAttribute(phase2b_kernel, cudaFuncAttributeMaxDynamicSharedMemorySize, P2_SMEM);

    pack_ze<<<8192, 256>>>(ze);
    pack_cb<<<(K_TOT * D_DIM) / 256, 256>>>(cb);
    norm_cb<<<K_TOT / 8, 256>>>(cb);
    norm_z<<<M_TOT / 8, 256>>>(ze);
    phase1_kernel<<<(M_TOT / BM) * 4, 512, P1_SMEM>>>();
    p1_merge<<<M_TOT / 256, 256>>>();
    rescore_kernel<<<512, 256>>>(ze, cb);
    phase2a<<<1024, 256>>>(ze);
    phase2b_kernel<<<(M_TOT / BM) * 32, 512, P2_SMEM>>>();
    gather_kernel<<<M_TOT, 128>>>(cb, out);
}

// round 16
// speedup vs baseline: 1.0459x; 1.0459x over previous
#include <cuda_runtime.h>
#include <cuda_fp16.h>
#include <cstdint>

#define M_TOT 32768
#define K_TOT 8192
#define D_DIM 512
#define BM 128
#define BN 256

#define A_TILE_HALF 4096              // per (mtile,kt): hi plane (2048 halves used)
#define B_TILE_HALF 8192              // per (g,kt): interleaved hi|lo frag layout (phase2)
#define B1_TILE_HALF 4096             // per (g,kt): hi-only pair-packed (phase1)

#define EPS_ACC 0.015f
#define MAX_CAND 8

// ---- device scratch -----------------------------------------------------------
__device__ float    g_hn[K_TOT];
__device__ int      g_idx[M_TOT];
__device__ __half   g_A [(size_t)M_TOT * D_DIM * 2];
__device__ __half   g_A2[(size_t)M_TOT * D_DIM * 2];
__device__ __half   g_B [(size_t)K_TOT * D_DIM * 2];
__device__ __half   g_Bh1[(size_t)K_TOT * D_DIM];
__device__ float    g_T[M_TOT];
__device__ int      g_dirty[M_TOT];                    // full-GEMM fallback tokens
__device__ int      g_cnt;
__device__ unsigned long long g_key[M_TOT];            // 0 = clean; else packed (score,~idx)
__device__ unsigned g_mbh_bits, g_mbl_bits;
// phase1 per-lane records, transposed for coalesced merge reads: [unit(64)][tok]
__device__ float    g_l1[64 * M_TOT];
__device__ float    g_l2[64 * M_TOT];
__device__ int      g_li[64 * M_TOT];
// rescore lists
__device__ int      g_rtok[M_TOT * MAX_CAND];
__device__ int      g_rcode[M_TOT * MAX_CAND];
__device__ int      g_rcnt;

// ---- helpers --------------------------------------------------------------------
__device__ __forceinline__ uint32_t smem_u32(const void* p) {
    uint32_t a;
    asm("{ .reg .u64 t; cvta.to.shared.u64 t, %1; cvt.u32.u64 %0, t; }" : "=r"(a) : "l"(p));
    return a;
}
__device__ __forceinline__ void cp16(uint32_t dst, const void* src) {
    asm volatile("cp.async.cg.shared.global [%0], [%1], 16;" :: "r"(dst), "l"(src) : "memory");
}
#define CP_COMMIT() asm volatile("cp.async.commit_group;" ::: "memory")
#define CP_WAIT2()  asm volatile("cp.async.wait_group 2;" ::: "memory")
#define CP_WAIT1()  asm volatile("cp.async.wait_group 1;" ::: "memory")
#define CP_WAIT0()  asm volatile("cp.async.wait_group 0;" ::: "memory")

__device__ __forceinline__ void mma16(float* c, const uint4& a, uint32_t b0, uint32_t b1) {
    asm volatile(
        "mma.sync.aligned.m16n8k16.row.col.f32.f16.f16.f32 "
        "{%0,%1,%2,%3}, {%4,%5,%6,%7}, {%8,%9}, {%0,%1,%2,%3};"
        : "+f"(c[0]), "+f"(c[1]), "+f"(c[2]), "+f"(c[3])
        : "r"(a.x), "r"(a.y), "r"(a.z), "r"(a.w), "r"(b0), "r"(b1));
}

// ---- prep ------------------------------------------------------------------------
__global__ void pack_ze(const float* __restrict__ ze) {
    int idx  = blockIdx.x * blockDim.x + threadIdx.x;
    int lane = idx & 31, mblk = (idx >> 5) & 7, kt = (idx >> 8) & 31, mt = idx >> 13;
    int q = lane >> 2, r4 = lane & 3;
    __half hi[8];
#pragma unroll
    for (int jj = 0; jj < 4; ++jj) {
        int rhalf = jj & 1, khalf = jj >> 1;
        int m = mt * 128 + mblk * 16 + rhalf * 8 + q;
        int d = kt * 16 + khalf * 8 + r4 * 2;
        float2 f = *reinterpret_cast<const float2*>(ze + (size_t)m * D_DIM + d);
        hi[jj * 2 + 0] = __float2half_rn(f.x);
        hi[jj * 2 + 1] = __float2half_rn(f.y);
    }
    size_t base = ((size_t)(mt * 32 + kt)) * A_TILE_HALF + (size_t)(mblk * 32 + lane) * 8;
    *reinterpret_cast<uint4*>(&g_A[base]) = *reinterpret_cast<uint4*>(hi);
}
__global__ void pack_cb(const float* __restrict__ cb) {
    int i = blockIdx.x * blockDim.x + threadIdx.x;
    float f = cb[i];
    __half hi = __float2half_rn(f);
    __half lo = __float2half_rn(f - __half2float(hi));
    int n = i >> 9, d = i & 511;
    int g = n >> 8, nr = n & 255, nblk = nr >> 3, q = nr & 7;
    int kt = d >> 4, kk = d & 15, par = kk & 1, r4 = (kk >> 1) & 3, khalf = kk >> 3;
    int lane = q * 4 + r4;
    size_t base = ((size_t)(g * 32 + kt)) * B_TILE_HALF + (size_t)(nblk * 32 + lane) * 8;
    g_B[base + khalf * 2 + par]     = hi;
    g_B[base + 4 + khalf * 2 + par] = lo;
    int pair = nblk >> 1, side = nblk & 1;
    size_t b1 = ((size_t)(g * 32 + kt)) * B1_TILE_HALF + (size_t)(pair * 32 + lane) * 8;
    g_Bh1[b1 + side * 4 + khalf * 2 + par] = hi;
}
__global__ void norm_cb(const float* __restrict__ cb) {
    int code = (blockIdx.x * blockDim.x + threadIdx.x) >> 5;
    int lane = threadIdx.x & 31;
    const float4* row = reinterpret_cast<const float4*>(cb + (size_t)code * D_DIM);
    float s = 0.0f, nh2 = 0.0f, nl2 = 0.0f;
#pragma unroll
    for (int t = 0; t < 4; ++t) {
        float4 v = row[lane + 32 * t];
        float vv[4] = { v.x, v.y, v.z, v.w };
#pragma unroll
        for (int e = 0; e < 4; ++e) {
            float f = vv[e];
            s += f * f;
            float h = __half2float(__float2half_rn(f));
            float l = __half2float(__float2half_rn(f - h));
            nh2 += h * h;
            nl2 += l * l;
        }
    }
#pragma unroll
    for (int off = 16; off > 0; off >>= 1) {
        s   += __shfl_xor_sync(0xffffffffu, s, off);
        nh2 += __shfl_xor_sync(0xffffffffu, nh2, off);
        nl2 += __shfl_xor_sync(0xffffffffu, nl2, off);
    }
    if (lane == 0) {
        g_hn[code] = 0.5f * s;
        atomicMax(&g_mbh_bits, __float_as_uint(sqrtf(nh2)));
        atomicMax(&g_mbl_bits, __float_as_uint(sqrtf(nl2)));
    }
}
__global__ void norm_z(const float* __restrict__ ze) {
    if (blockIdx.x == 0 && threadIdx.x == 0) { g_cnt = 0; g_rcnt = 0; }
    int tok  = (blockIdx.x * blockDim.x + threadIdx.x) >> 5;
    int lane = threadIdx.x & 31;
    const float4* row = reinterpret_cast<const float4*>(ze + (size_t)tok * D_DIM);
    float nh2 = 0.0f, nl2 = 0.0f;
#pragma unroll
    for (int t = 0; t < 4; ++t) {
        float4 v = row[lane + 32 * t];
        float vv[4] = { v.x, v.y, v.z, v.w };
#pragma unroll
        for (int e = 0; e < 4; ++e) {
            float f = vv[e];
            float h = __half2float(__float2half_rn(f));
            float l = __half2float(__float2half_rn(f - h));
            nh2 += h * h;
            nl2 += l * l;
        }
    }
#pragma unroll
    for (int off = 16; off > 0; off >>= 1) {
        nh2 += __shfl_xor_sync(0xffffffffu, nh2, off);
        nl2 += __shfl_xor_sync(0xffffffffu, nl2, off);
    }
    if (lane == 0) {
        float mbh = __uint_as_float(g_mbh_bits);
        float mbl = __uint_as_float(g_mbl_bits);
        float anh = sqrtf(nh2), anl = sqrtf(nl2);
        g_T[tok] = anh * mbl + anl * mbh + anl * mbl + EPS_ACC;
        g_key[tok] = 0ull;
    }
}

// ---- PHASE 1: hh-only GEMM + per-lane top-2, K split x4 (R14 pipeline config) --------
#define P1_PAIR 24576
#define P1_SMEM (4 * P1_PAIR)
#define P1_PAIRS 128
__global__ void __launch_bounds__(512, 1) phase1_kernel() {
    extern __shared__ __align__(16) char smem[];
    const uint32_t sbase = smem_u32(smem);
    const int tid = threadIdx.x, wid = tid >> 5, lane = tid & 31;
    const int wm = wid >> 2, wn = wid & 3, q = lane >> 2, r4 = lane & 3;
    const int mtile = blockIdx.x >> 2, ks = blockIdx.x & 3;
    const int m0 = mtile * BM;

    float acc[2][8][4];
    float t1[2][2], t2[2][2];
    int   ti[2][2];
#pragma unroll
    for (int mf = 0; mf < 2; ++mf)
#pragma unroll
        for (int h = 0; h < 2; ++h) { t1[mf][h] = -3.0e38f; t2[mf][h] = -3.0e38f; ti[mf][h] = 0; }
#pragma unroll
    for (int mf = 0; mf < 2; ++mf)
#pragma unroll
        for (int nf = 0; nf < 8; ++nf)
#pragma unroll
            for (int c = 0; c < 4; ++c) acc[mf][nf][c] = 0.0f;

    auto issue_pair = [&](int p) {
        const int t0 = 2 * p, kt = t0 & 31, g = ks * 8 + (t0 >> 5);
        const uint32_t stw = sbase + (uint32_t)(p & 3) * P1_PAIR;
        const __half* aG = g_A   + ((size_t)(mtile * 32) + kt) * A_TILE_HALF;
        const __half* bG = g_Bh1 + ((size_t)(g * 32 + kt)) * B1_TILE_HALF;
        int sub = tid >> 8, off = tid & 255;
        cp16(stw + sub * 4096 + off * 16, aG + (size_t)sub * A_TILE_HALF + off * 8);
#pragma unroll
        for (int i = 0; i < 2; ++i) {
            int seg = tid + i * 512;
            cp16(stw + 8192 + seg * 16, bG + (size_t)seg * 8);
        }
        CP_COMMIT();
    };
    issue_pair(0); issue_pair(1); issue_pair(2);

    for (int p = 0; p < P1_PAIRS; ++p) {
        if (p < P1_PAIRS - 2)       { CP_WAIT2(); }
        else if (p == P1_PAIRS - 2) { CP_WAIT1(); }
        else                        { CP_WAIT0(); }
        __syncthreads();
        if (p + 3 < P1_PAIRS) issue_pair(p + 3);

        const char* stg = smem + (p & 3) * P1_PAIR;
#pragma unroll
        for (int sub = 0; sub < 2; ++sub) {
            const char* stA = stg + sub * 4096;
            const char* stB = stg + 8192 + sub * 8192;
            uint4 ah0 = *reinterpret_cast<const uint4*>(stA + (size_t)((wm * 2 + 0) * 32 + lane) * 16);
            uint4 ah1 = *reinterpret_cast<const uint4*>(stA + (size_t)((wm * 2 + 1) * 32 + lane) * 16);
#pragma unroll
            for (int p4 = 0; p4 < 4; ++p4) {
                uint4 b = *reinterpret_cast<const uint4*>(
                    stB + (size_t)((wn * 4 + p4) * 32 + lane) * 16);
                mma16(acc[0][2 * p4],     ah0, b.x, b.y);
                mma16(acc[1][2 * p4],     ah1, b.x, b.y);
                mma16(acc[0][2 * p4 + 1], ah0, b.z, b.w);
                mma16(acc[1][2 * p4 + 1], ah1, b.z, b.w);
            }
        }

        if ((p & 15) == 15) {
            const int g = ks * 8 + (p >> 4);
#pragma unroll
            for (int nf = 0; nf < 8; ++nf) {
                int gc = g * BN + wn * 64 + nf * 8 + 2 * r4;
                float h0 = __ldg(&g_hn[gc]), h1 = __ldg(&g_hn[gc + 1]);
#pragma unroll
                for (int mf = 0; mf < 2; ++mf) {
                    float s0 = acc[mf][nf][0] - h0, s1 = acc[mf][nf][1] - h1;
                    float s2 = acc[mf][nf][2] - h0, s3 = acc[mf][nf][3] - h1;
                    if (s0 > t1[mf][0]) { t2[mf][0] = t1[mf][0]; t1[mf][0] = s0; ti[mf][0] = gc; }
                    else if (s0 > t2[mf][0]) t2[mf][0] = s0;
                    if (s1 > t1[mf][0]) { t2[mf][0] = t1[mf][0]; t1[mf][0] = s1; ti[mf][0] = gc + 1; }
                    else if (s1 > t2[mf][0]) t2[mf][0] = s1;
                    if (s2 > t1[mf][1]) { t2[mf][1] = t1[mf][1]; t1[mf][1] = s2; ti[mf][1] = gc; }
                    else if (s2 > t2[mf][1]) t2[mf][1] = s2;
                    if (s3 > t1[mf][1]) { t2[mf][1] = t1[mf][1]; t1[mf][1] = s3; ti[mf][1] = gc + 1; }
                    else if (s3 > t2[mf][1]) t2[mf][1] = s3;
                    acc[mf][nf][0] = 0.0f; acc[mf][nf][1] = 0.0f;
                    acc[mf][nf][2] = 0.0f; acc[mf][nf][3] = 0.0f;
                }
            }
        }
    }

    // Per-lane records, transposed layout [unit][tok]; unit = ks*16 + wn*4 + r4.
    const int unit = ks * 16 + wn * 4 + r4;
#pragma unroll
    for (int mf = 0; mf < 2; ++mf)
#pragma unroll
        for (int h = 0; h < 2; ++h) {
            int row = wm * 32 + mf * 16 + h * 8 + q;
            size_t slot = (size_t)unit * M_TOT + (m0 + row);
            g_l1[slot] = t1[mf][h];
            g_l2[slot] = t2[mf][h];
            g_li[slot] = ti[mf][h];
        }
}

// ---- merge: lane-level certification ---------------------------------------------------
__global__ void p1_merge() {
    int tok = blockIdx.x * blockDim.x + threadIdx.x;
    float H1 = -3.0e38f, mT2 = -3.0e38f;
    int bi = 0;
    for (int u = 0; u < 64; ++u) {
        size_t s = (size_t)u * M_TOT + tok;
        float o1 = g_l1[s];
        int   oi = g_li[s];
        if (o1 > H1 || (o1 == H1 && oi < bi)) { mT2 = fmaxf(mT2, H1); H1 = o1; bi = oi; }
        else mT2 = fmaxf(mT2, o1);
        mT2 = fmaxf(mT2, g_l2[s]);
    }
    float thr = H1 - 2.0f * g_T[tok];
    g_idx[tok] = bi;
    if (mT2 < thr) return;                             // certified clean

    int cand[MAX_CAND];
    int nc = 0;
    bool overflow = false;
    for (int u = 0; u < 64 && !overflow; ++u) {
        size_t s = (size_t)u * M_TOT + tok;
        if (g_l2[s] >= thr) overflow = true;
        float o1 = g_l1[s];
        if (o1 >= thr) {
            if (nc < MAX_CAND) cand[nc++] = g_li[s];
            else overflow = true;
        }
    }
    if (overflow) {
        int pos = atomicAdd(&g_cnt, 1);
        g_dirty[pos] = tok;
        return;
    }
    int rb = atomicAdd(&g_rcnt, nc);
    for (int c = 0; c < nc; ++c) { g_rtok[rb + c] = tok; g_rcode[rb + c] = cand[c]; }
}

// ---- exact fp32 rescore: one warp per (token, candidate) -------------------------------
__global__ void rescore_kernel(const float* __restrict__ ze, const float* __restrict__ cb) {
    int w    = (blockIdx.x * blockDim.x + threadIdx.x) >> 5;
    int lane = threadIdx.x & 31;
    int nw   = (gridDim.x * blockDim.x) >> 5;
    int total = g_rcnt;
    for (int p = w; p < total; p += nw) {
        int tok = g_rtok[p], code = g_rcode[p];
        const float4* za = reinterpret_cast<const float4*>(ze + (size_t)tok  * D_DIM);
        const float4* ca = reinterpret_cast<const float4*>(cb + (size_t)code * D_DIM);
        float s = 0.0f;
#pragma unroll
        for (int t = 0; t < 4; ++t) {
            float4 a = za[lane + 32 * t], b = ca[lane + 32 * t];
            s += a.x * b.x + a.y * b.y + a.z * b.z + a.w * b.w;
        }
#pragma unroll
        for (int off = 16; off > 0; off >>= 1) s += __shfl_xor_sync(0xffffffffu, s, off);
        if (lane == 0) {
            float sc = s - g_hn[code];
            uint32_t ub = __float_as_uint(sc);
            ub = (sc >= 0.0f) ? (ub | 0x80000000u) : ~ub;
            unsigned long long key = ((unsigned long long)ub << 32) | (unsigned)(~code);
            atomicMax(&g_key[tok], key);
        }
    }
}

// ---- full-GEMM fallback (rare): repack + 3-term, K split x32 ---------------------------
__global__ void phase2a(const float* __restrict__ ze) {
    int total = g_cnt * 512;
    for (int i = blockIdx.x * blockDim.x + threadIdx.x; i < total;
         i += gridDim.x * blockDim.x) {
        int s = i >> 9, d = i & 511;
        int tok = g_dirty[s];
        float f = ze[(size_t)tok * D_DIM + d];
        __half hi = __float2half_rn(f);
        __half lo = __float2half_rn(f - __half2float(hi));
        int mt = s >> 7, mr = s & 127, mblk = mr >> 4, row = mr & 15;
        int q = row & 7, rhalf = row >> 3;
        int kt = d >> 4, kk = d & 15, par = kk & 1, r4 = (kk >> 1) & 3, khalf = kk >> 3;
        int lane = q * 4 + r4, reg = rhalf + 2 * khalf;
        size_t base = ((size_t)(mt * 32 + kt)) * A_TILE_HALF + (size_t)(mblk * 32 + lane) * 8;
        g_A2[base + reg * 2 + par]        = hi;
        g_A2[base + 2048 + reg * 2 + par] = lo;
    }
}
#define P2_STG 24576
#define P2_SCR (3 * P2_STG)
#define P2_SMEM (P2_SCR + 4096)
#define P2_TILES 32
__global__ void __launch_bounds__(512, 1) phase2b_kernel() {
    const int cnt = g_cnt;
    const int mtile = blockIdx.x >> 5;
    const int ks    = blockIdx.x & 31;
    if (mtile * BM >= cnt) return;

    extern __shared__ __align__(16) char smem[];
    const uint32_t sbase = smem_u32(smem);
    const int tid = threadIdx.x, wid = tid >> 5, lane = tid & 31;
    const int wm = wid >> 2, wn = wid & 3, q = lane >> 2, r4 = lane & 3;
    const int m0 = mtile * BM;

    float* s_sb = reinterpret_cast<float*>(smem + P2_SCR);
    int*   s_si = reinterpret_cast<int*>(smem + P2_SCR + 2048);

    float acc[2][8][4];
#pragma unroll
    for (int mf = 0; mf < 2; ++mf)
#pragma unroll
        for (int nf = 0; nf < 8; ++nf)
#pragma unroll
            for (int c = 0; c < 4; ++c) acc[mf][nf][c] = 0.0f;

    auto issue_tile = [&](int t) {
        const uint32_t stw = sbase + (uint32_t)(t % 3) * P2_STG;
        const __half* aG = g_A2 + ((size_t)(mtile * 32) + t) * A_TILE_HALF;
        const __half* bG = g_B  + ((size_t)(ks * 32 + t)) * B_TILE_HALF;
        cp16(stw + tid * 16, aG + tid * 8);
#pragma unroll
        for (int i = 0; i < 2; ++i) {
            int seg = tid + i * 512;
            cp16(stw + 8192 + seg * 16, bG + seg * 8);
        }
        CP_COMMIT();
    };
    issue_tile(0); issue_tile(1);

    for (int t = 0; t < P2_TILES; ++t) {
        if (t < P2_TILES - 1) { CP_WAIT1(); } else { CP_WAIT0(); }
        __syncthreads();
        if (t + 2 < P2_TILES) issue_tile(t + 2);

        const char* st = smem + (t % 3) * P2_STG;
        uint4 ah[2], al[2];
#pragma unroll
        for (int mf = 0; mf < 2; ++mf) {
            ah[mf] = *reinterpret_cast<const uint4*>(
                st + (size_t)((wm * 2 + mf) * 32 + lane) * 16);
            al[mf] = *reinterpret_cast<const uint4*>(
                st + 4096 + (size_t)((wm * 2 + mf) * 32 + lane) * 16);
        }
#pragma unroll
        for (int nf = 0; nf < 8; ++nf) {
            uint4 b = *reinterpret_cast<const uint4*>(
                st + 8192 + (size_t)((wn * 8 + nf) * 32 + lane) * 16);
#pragma unroll
            for (int mf = 0; mf < 2; ++mf) {
                mma16(acc[mf][nf], ah[mf], b.x, b.y);
                mma16(acc[mf][nf], ah[mf], b.z, b.w);
                mma16(acc[mf][nf], al[mf], b.x, b.y);
            }
        }
    }

    float bestv[2][2];
    int   besti[2][2];
#pragma unroll
    for (int mf = 0; mf < 2; ++mf)
#pragma unroll
        for (int h = 0; h < 2; ++h) { bestv[mf][h] = -3.0e38f; besti[mf][h] = 0; }
#pragma unroll
    for (int nf = 0; nf < 8; ++nf) {
        int gc = ks * BN + wn * 64 + nf * 8 + 2 * r4;
        float h0 = __ldg(&g_hn[gc]), h1 = __ldg(&g_hn[gc + 1]);
#pragma unroll
        for (int mf = 0; mf < 2; ++mf) {
            float s0 = acc[mf][nf][0] - h0, s1 = acc[mf][nf][1] - h1;
            float s2 = acc[mf][nf][2] - h0, s3 = acc[mf][nf][3] - h1;
            if (s0 > bestv[mf][0]) { bestv[mf][0] = s0; besti[mf][0] = gc; }
            if (s1 > bestv[mf][0]) { bestv[mf][0] = s1; besti[mf][0] = gc + 1; }
            if (s2 > bestv[mf][1]) { bestv[mf][1] = s2; besti[mf][1] = gc; }
            if (s3 > bestv[mf][1]) { bestv[mf][1] = s3; besti[mf][1] = gc + 1; }
        }
    }
#pragma unroll
    for (int off = 1; off <= 2; off <<= 1) {
#pragma unroll
        for (int mf = 0; mf < 2; ++mf)
#pragma unroll
            for (int h = 0; h < 2; ++h) {
                float ov = __shfl_xor_sync(0xffffffffu, bestv[mf][h], off);
                int   oi = __shfl_xor_sync(0xffffffffu, besti[mf][h], off);
                if (ov > bestv[mf][h] || (ov == bestv[mf][h] && oi < besti[mf][h])) {
                    bestv[mf][h] = ov; besti[mf][h] = oi;
                }
            }
    }
    if (r4 == 0) {
#pragma unroll
        for (int mf = 0; mf < 2; ++mf)
#pragma unroll
            for (int h = 0; h < 2; ++h) {
                int rl = wm * 32 + mf * 16 + h * 8 + q;
                s_sb[rl * 4 + wn] = bestv[mf][h];
                s_si[rl * 4 + wn] = besti[mf][h];
            }
    }
    __syncthreads();
    if (tid < BM && (m0 + tid) < cnt) {
        float bv = s_sb[tid * 4]; int bi = s_si[tid * 4];
#pragma unroll
        for (int w = 1; w < 4; ++w) {
            float ov = s_sb[tid * 4 + w]; int oi = s_si[tid * 4 + w];
            if (ov > bv || (ov == bv && oi < bi)) { bv = ov; bi = oi; }
        }
        uint32_t ub = __float_as_uint(bv);
        ub = (bv >= 0.0f) ? (ub | 0x80000000u) : ~ub;
        unsigned long long key = ((unsigned long long)ub << 32) | (unsigned)(~bi);
        atomicMax(&g_key[g_dirty[m0 + tid]], key);
    }
}

// ---- gather (fused finalize: decode g_key when the token was repaired) -----------------
__global__ void gather_kernel(const float* __restrict__ cb, float* __restrict__ out) {
    int m = blockIdx.x;
    unsigned long long key = g_key[m];
    int k = key ? (int)(~(unsigned)(key & 0xFFFFFFFFull)) : g_idx[m];
    const float4* src = reinterpret_cast<const float4*>(cb + (size_t)k * D_DIM);
    float4*       dst = reinterpret_cast<float4*>(out + (size_t)m * D_DIM);
    dst[threadIdx.x] = src[threadIdx.x];
}

// ---- entry ------------------------------------------------------------------------------
extern "C" void kernel_launch(void* const* d_in, const int* in_sizes, int n_in,
                              void* d_out, int out_size) {
    const float* ze = (const float*)d_in[0];
    const float* cb = (const float*)d_in[1];
    float* out = (float*)d_out;

    cudaFuncSetAttribute(phase1_kernel,  cudaFuncAttributeMaxDynamicSharedMemorySize, P1_SMEM);
    cudaFuncSetAttribute(phase2b_kernel, cudaFuncAttributeMaxDynamicSharedMemorySize, P2_SMEM);

    pack_ze<<<8192, 256>>>(ze);
    pack_cb<<<(K_TOT * D_DIM) / 256, 256>>>(cb);
    norm_cb<<<K_TOT / 8, 256>>>(cb);
    norm_z<<<M_TOT / 8, 256>>>(ze);
    phase1_kernel<<<(M_TOT / BM) * 4, 512, P1_SMEM>>>();
    p1_merge<<<M_TOT / 256, 256>>>();
    rescore_kernel<<<512, 256>>>(ze, cb);
    phase2a<<<1024, 256>>>(ze);
    phase2b_kernel<<<(M_TOT / BM) * 32, 512, P2_SMEM>>>();
    gather_kernel<<<M_TOT, 128>>>(cb, out);
}